// round 15
// baseline (speedup 1.0000x reference)
#include <cuda_runtime.h>
#include <cuda_bf16.h>
#include <stdint.h>

// Problem constants
#define NN 8192      // nodes
#define SS 8192      // structures
#define FF 64        // features
#define OO 64        // out features
#define K0c 0.5f
#define K1c 0.05f
#define K2c (-0.05f)
#define K3c 0.05f

// ---------------------------------------------------------------------------
// Device scratch (static allocation — allowed)
// ---------------------------------------------------------------------------
__device__ __nv_bfloat16 g_xThi[FF * NN];   // x^T split hi  [f][k]
__device__ __nv_bfloat16 g_xTlo[FF * NN];   // x^T split lo  [f][k]
__device__ float g_ypart[16][NN * FF];      // [mat*8 + ksplit][n][f]
__device__ int   g_cnt[SS];
__device__ int   g_members[SS * 10];
__device__ float g_acc2[NN * FF];

// ---------------------------------------------------------------------------
// portable PTX helpers (no sm_103a-only features)
// ---------------------------------------------------------------------------
#define LDSM_X4(r0, r1, r2, r3, addr) \
    asm volatile("ldmatrix.sync.aligned.m8n8.x4.shared.b16 {%0,%1,%2,%3}, [%4];" \
                 : "=r"(r0), "=r"(r1), "=r"(r2), "=r"(r3) : "r"(addr))

#define MMA16816(c, a, b0, b1) \
    asm volatile("mma.sync.aligned.m16n8k16.row.col.f32.bf16.bf16.f32 " \
                 "{%0,%1,%2,%3}, {%4,%5,%6,%7}, {%8,%9}, {%0,%1,%2,%3};" \
                 : "+f"((c)[0]), "+f"((c)[1]), "+f"((c)[2]), "+f"((c)[3]) \
                 : "r"((a)[0]), "r"((a)[1]), "r"((a)[2]), "r"((a)[3]), \
                   "r"(b0), "r"(b1))

#define CP_ASYNC16(dst, src) \
    asm volatile("cp.async.cg.shared.global [%0], [%1], 16;" \
                 :: "r"(dst), "l"(src) : "memory")
#define CP_COMMIT() asm volatile("cp.async.commit_group;" ::: "memory")
#define CP_WAIT1()  asm volatile("cp.async.wait_group 1;" ::: "memory")

__device__ __forceinline__ uint32_t smem_u32(const void* p) {
    return (uint32_t)__cvta_generic_to_shared(p);
}

// ---------------------------------------------------------------------------
// Kernel: split x into transposed bf16 hi/lo pairs + zero accumulators
// ---------------------------------------------------------------------------
__global__ void split_x_kernel(const float* __restrict__ x) {
    int t = blockIdx.x * 256 + threadIdx.x;       // 0 .. NN*FF-1
    int i = t >> 6, f = t & 63;
    float v = x[t];
    __nv_bfloat16 h = __float2bfloat16(v);
    float r = v - __bfloat162float(h);
    g_xThi[f * NN + i] = h;
    g_xTlo[f * NN + i] = __float2bfloat16(r);
    g_acc2[t] = 0.f;
    if (t < SS) g_cnt[t] = 0;
}

// ---------------------------------------------------------------------------
// Kernel: per-structure tanh term + scatter into acc2
// ---------------------------------------------------------------------------
__global__ void struct_kernel(const float* __restrict__ x) {
    int wid = threadIdx.x >> 5, lid = threadIdx.x & 31;
    int s = blockIdx.x * 8 + wid;
    int m = g_cnt[s];
    if (m != 3 && m != 4 && m != 10) return;
    int mem[10];
    int first = 0x7FFFFFFF;
#pragma unroll 10
    for (int j = 0; j < 10; j++) {
        if (j < m) {
            mem[j] = g_members[s * 10 + j];
            first = min(first, mem[j]);
        }
    }
    float sa = 0.f, sb = 0.f;
    for (int j = 0; j < m; j++) {
        const float* xr = x + mem[j] * FF;
        sa += xr[lid];
        sb += xr[lid + 32];
    }
    const float* xf = x + first * FF;
    float fm = (float)m;
    float ta = tanhf(fm * xf[lid]      - sa) * K3c;
    float tb = tanhf(fm * xf[lid + 32] - sb) * K3c;
    for (int j = 0; j < m; j++) {
        atomicAdd(&g_acc2[mem[j] * FF + lid],      ta);
        atomicAdd(&g_acc2[mem[j] * FF + 32 + lid], tb);
    }
}

// ---------------------------------------------------------------------------
// Fused GEMM + incidence extraction (R6 structure, proven best).
// GEMM: y = Lap @ x, mma.sync bf16-split (3 terms), cp.async 3-stage pipe.
// BM=64, BN=64, TKC=32, 128 threads (4 warps, 2x2), 4 CTAs/SM.
// Each CTA extracts a 128KB slice of the incidence matrix (pre-phase,
// overlapped across waves at grid level).
// grid = 2048 (128 mtiles x 8 ksplits x 2 matrices).
// ---------------------------------------------------------------------------
#define TKC 32
#define KSPLIT 8
#define KPER (NN / KSPLIT)          // 1024
#define GITERS (KPER / TKC)         // 32
#define NSTAGE 3
// stage: A fp32 64 rows x 160B = 10240; Bhi 64x64B = 4096; Blo 4096
#define A_ROW_B 160
#define B_OFF   10240
#define BL_OFF  14336
#define STAGE_BYTES 18432
#define GEMM_SMEM (NSTAGE * STAGE_BYTES)

// SW64 swizzle for 64B rows: chunk c (16B) at row r -> c ^ ((r>>1)&3)
#define SW64C(r, c) (((c) ^ (((r) >> 1) & 3)) << 4)

__device__ __forceinline__ void splitf2(float2 v, uint32_t& h, uint32_t& l) {
    __nv_bfloat162 hh = __float22bfloat162_rn(v);
    float hx = __bfloat162float(__low2bfloat16(hh));
    float hy = __bfloat162float(__high2bfloat16(hh));
    __nv_bfloat162 ll = __floats2bfloat162_rn(v.x - hx, v.y - hy);
    h = *(uint32_t*)&hh;
    l = *(uint32_t*)&ll;
}

__device__ __forceinline__ void issue_stage(const float* __restrict__ A,
                                            int m0, int k0, int tid,
                                            uint32_t sstage) {
    // A: 64 rows x 32 fp32 (128B = 8 x 16B chunks) -> 512 chunks, 4/thread
#pragma unroll
    for (int j = 0; j < 4; j++) {
        int q = tid + j * 128;
        int row = q >> 3, c = q & 7;
        uint32_t dst = sstage + row * A_ROW_B + c * 16;
        const float* src = A + (size_t)(m0 + row) * NN + k0 + c * 4;
        CP_ASYNC16(dst, src);
    }
    // B hi/lo: 64 rows x 32 bf16 = 64B/row, SW64 packed -> 256 chunks each
#pragma unroll
    for (int j = 0; j < 2; j++) {
        int q = tid + j * 128;
        int row = q >> 2, c = q & 3;
        uint32_t sw = (uint32_t)(row * 64 + SW64C(row, c));
        const char* srch = (const char*)(g_xThi + (size_t)row * NN + k0 + c * 8);
        const char* srcl = (const char*)(g_xTlo + (size_t)row * NN + k0 + c * 8);
        CP_ASYNC16(sstage + B_OFF + sw, srch);
        CP_ASYNC16(sstage + BL_OFF + sw, srcl);
    }
    CP_COMMIT();
}

__global__ void __launch_bounds__(128, 4)
gemm_extract_kernel(const float* __restrict__ lapP, const float* __restrict__ lapN,
                    const float* __restrict__ inc) {
    extern __shared__ char smem[];
    const int tid = threadIdx.x;
    const int wid = tid >> 5;
    const int lane = tid & 31;
    const int bid = blockIdx.x;
    const int mat = bid >> 10;
    const int rest = bid & 1023;
    const int ks = rest & 7;
    const int mtile = rest >> 3;
    const float* A = mat ? lapN : lapP;
    float* dst = g_ypart[mat * 8 + ks];
    const int m0 = mtile * 64;
    const int kb = ks * KPER;

    const int warp_m = (wid & 1) * 32;   // 2 warps along M
    const int warp_n = (wid >> 1) * 32;  // 2 warps along N

    const uint32_t sbase = smem_u32(smem);

    float acc[2][4][4];
#pragma unroll
    for (int mt = 0; mt < 2; mt++)
#pragma unroll
        for (int nt = 0; nt < 4; nt++)
#pragma unroll
            for (int j = 0; j < 4; j++) acc[mt][nt][j] = 0.f;

    // prologue: issue first NSTAGE-1 stages (data streams during extract)
    issue_stage(A, m0, kb, tid, sbase);
    issue_stage(A, m0, kb + TKC, tid, sbase + STAGE_BYTES);

    // ---- fused incidence extraction: this CTA's 8192-float4 slice ----
    {
        const float4* inc4 = (const float4*)inc;
        int base = bid * 8192;
        for (int j = 0; j < 64; j++) {
            int q = base + j * 128 + tid;
            float4 v = __ldcs(inc4 + q);
            int e = q * 4;
            int i = e >> 13;        // row (node)
            int s = e & 8191;       // column (structure)
            float vv[4] = {v.x, v.y, v.z, v.w};
#pragma unroll
            for (int u = 0; u < 4; u++) {
                if (vv[u] != 0.0f) {
                    int p = atomicAdd(&g_cnt[s + u], 1);
                    if (p < 10) g_members[(s + u) * 10 + p] = i;
                }
            }
        }
    }

    // ---- GEMM mainloop ----
    for (int it = 0; it < GITERS; ++it) {
        CP_WAIT1();            // 2 groups pending -> stage `it` resident
        __syncthreads();

        if (it + NSTAGE - 1 < GITERS)
            issue_stage(A, m0, kb + (it + NSTAGE - 1) * TKC, tid,
                        sbase + ((it + NSTAGE - 1) % NSTAGE) * STAGE_BYTES);
        else
            CP_COMMIT();       // empty group keeps pending count at 2

        const uint32_t sstage = sbase + (it % NSTAGE) * STAGE_BYTES;
        const char* sa = smem + (it % NSTAGE) * STAGE_BYTES;

#pragma unroll
        for (int kc = 0; kc < 2; kc++) {
            // ---- A fragments: LDS fp32 + split in registers ----
            uint32_t ah[2][4], al[2][4];
#pragma unroll
            for (int mt = 0; mt < 2; mt++) {
                int row0 = warp_m + mt * 16 + (lane >> 2);
                int kbyt = kc * 64 + (lane & 3) * 8;
                const char* p = sa + row0 * A_ROW_B + kbyt;
                float2 v0 = *(const float2*)(p);
                float2 v1 = *(const float2*)(p + 8 * A_ROW_B);
                float2 v2 = *(const float2*)(p + 32);
                float2 v3 = *(const float2*)(p + 8 * A_ROW_B + 32);
                splitf2(v0, ah[mt][0], al[mt][0]);
                splitf2(v1, ah[mt][1], al[mt][1]);
                splitf2(v2, ah[mt][2], al[mt][2]);
                splitf2(v3, ah[mt][3], al[mt][3]);
            }
            // ---- B fragments via ldmatrix from SW64-packed rows ----
            uint32_t bh[2][4], bl[2][4];
#pragma unroll
            for (int nt2 = 0; nt2 < 2; nt2++) {
                uint32_t grp = lane >> 3;
                uint32_t nrow = warp_n + nt2 * 16 + (grp >> 1) * 8 + (lane & 7);
                uint32_t c = kc * 2 + (grp & 1);
                uint32_t off = nrow * 64 + SW64C(nrow, c);
                LDSM_X4(bh[nt2][0], bh[nt2][1], bh[nt2][2], bh[nt2][3],
                        sstage + B_OFF + off);
                LDSM_X4(bl[nt2][0], bl[nt2][1], bl[nt2][2], bl[nt2][3],
                        sstage + BL_OFF + off);
            }
#pragma unroll
            for (int mt = 0; mt < 2; mt++) {
#pragma unroll
                for (int nt = 0; nt < 4; nt++) {
                    int n2 = nt >> 1, p = (nt & 1) * 2;
                    MMA16816(acc[mt][nt], ah[mt], bh[n2][p], bh[n2][p + 1]);
                    MMA16816(acc[mt][nt], ah[mt], bl[n2][p], bl[n2][p + 1]);
                    MMA16816(acc[mt][nt], al[mt], bh[n2][p], bh[n2][p + 1]);
                }
            }
        }
    }

    // ---- epilogue: write partial results ----
#pragma unroll
    for (int mt = 0; mt < 2; mt++) {
#pragma unroll
        for (int nt = 0; nt < 4; nt++) {
            int r0 = m0 + warp_m + mt * 16 + (lane >> 2);
            int c0 = warp_n + nt * 8 + (lane & 3) * 2;
            *(float2*)(dst + (size_t)r0 * FF + c0) =
                make_float2(acc[mt][nt][0], acc[mt][nt][1]);
            *(float2*)(dst + (size_t)(r0 + 8) * FF + c0) =
                make_float2(acc[mt][nt][2], acc[mt][nt][3]);
        }
    }
}

// ---------------------------------------------------------------------------
// Final fused kernel: out = (K0*x + K1*sin(yp) + K2*sin(yn) + acc2) @ W + bias
// ---------------------------------------------------------------------------
__global__ void final_kernel(const float* __restrict__ x, const float* __restrict__ w,
                             const float* __restrict__ bias, float* __restrict__ out) {
    __shared__ float wsm[FF * OO];
    __shared__ float vsm[4 * FF];
    int tid = threadIdx.x;
#pragma unroll
    for (int j = 0; j < 16; j++) wsm[tid + j * 256] = w[tid + j * 256];
    int r = tid >> 6, f = tid & 63;
    int i = blockIdx.x * 4 + r;
    int idx = i * FF + f;
    float yp = 0.f, yn = 0.f;
#pragma unroll
    for (int p = 0; p < 8; p++) yp += g_ypart[p][idx];
#pragma unroll
    for (int p = 8; p < 16; p++) yn += g_ypart[p][idx];
    float v = K0c * x[idx] + K1c * sinf(yp) + K2c * sinf(yn) + g_acc2[idx];
    vsm[r * FF + f] = v;
    __syncthreads();
    int o = f;
    float acc = bias[o];
#pragma unroll
    for (int ff = 0; ff < FF; ff++)
        acc += vsm[r * FF + ff] * wsm[ff * OO + o];
    out[i * OO + o] = acc;
}

// ---------------------------------------------------------------------------
// Launch
// ---------------------------------------------------------------------------
extern "C" void kernel_launch(void* const* d_in, const int* in_sizes, int n_in,
                              void* d_out, int out_size) {
    const float* x    = (const float*)d_in[0];
    const float* lapP = (const float*)d_in[1];
    const float* lapN = (const float*)d_in[2];
    const float* inc  = (const float*)d_in[3];
    const float* w    = (const float*)d_in[4];
    const float* bias = (const float*)d_in[5];
    float* out = (float*)d_out;

    cudaFuncSetAttribute(gemm_extract_kernel,
                         cudaFuncAttributeMaxDynamicSharedMemorySize, GEMM_SMEM);

    split_x_kernel<<<(NN * FF) / 256, 256>>>(x);
    gemm_extract_kernel<<<2048, 128, GEMM_SMEM>>>(lapP, lapN, inc);
    struct_kernel<<<SS / 8, 256>>>(x);
    final_kernel<<<NN / 4, 256>>>(x, w, bias, out);
}

// round 16
// speedup vs baseline: 1.1761x; 1.1761x over previous
#include <cuda_runtime.h>
#include <cuda_bf16.h>
#include <stdint.h>

// Problem constants
#define NN 8192      // nodes
#define SS 8192      // structures
#define FF 64        // features
#define OO 64        // out features
#define K0c 0.5f
#define K1c 0.05f
#define K2c (-0.05f)
#define K3c 0.05f

// ---------------------------------------------------------------------------
// Device scratch (static allocation — allowed)
// ---------------------------------------------------------------------------
__device__ __nv_bfloat16 g_xThi[FF * NN];   // x^T split hi  [f][k]
__device__ __nv_bfloat16 g_xTlo[FF * NN];   // x^T split lo  [f][k]
__device__ float g_ypart[16][NN * FF];      // [mat*8 + ksplit][n][f]
__device__ int   g_cnt[SS];
__device__ int   g_members[SS * 10];
__device__ float g_acc2[NN * FF];

// ---------------------------------------------------------------------------
// portable PTX helpers (no sm_103a-only features)
// ---------------------------------------------------------------------------
#define LDSM_X4(r0, r1, r2, r3, addr) \
    asm volatile("ldmatrix.sync.aligned.m8n8.x4.shared.b16 {%0,%1,%2,%3}, [%4];" \
                 : "=r"(r0), "=r"(r1), "=r"(r2), "=r"(r3) : "r"(addr))

#define MMA16816(c, a, b0, b1) \
    asm volatile("mma.sync.aligned.m16n8k16.row.col.f32.bf16.bf16.f32 " \
                 "{%0,%1,%2,%3}, {%4,%5,%6,%7}, {%8,%9}, {%0,%1,%2,%3};" \
                 : "+f"((c)[0]), "+f"((c)[1]), "+f"((c)[2]), "+f"((c)[3]) \
                 : "r"((a)[0]), "r"((a)[1]), "r"((a)[2]), "r"((a)[3]), \
                   "r"(b0), "r"(b1))

#define CP_ASYNC16(dst, src) \
    asm volatile("cp.async.cg.shared.global [%0], [%1], 16;" \
                 :: "r"(dst), "l"(src) : "memory")
#define CP_COMMIT() asm volatile("cp.async.commit_group;" ::: "memory")
#define CP_WAIT1()  asm volatile("cp.async.wait_group 1;" ::: "memory")

__device__ __forceinline__ uint32_t smem_u32(const void* p) {
    return (uint32_t)__cvta_generic_to_shared(p);
}

// ---------------------------------------------------------------------------
// Kernel: zero accumulators (must run every launch; scratch persists)
// ---------------------------------------------------------------------------
__global__ void zero_kernel() {
    int t = blockIdx.x * 256 + threadIdx.x;
    if (t < (NN * FF) / 4) ((float4*)g_acc2)[t] = make_float4(0.f, 0.f, 0.f, 0.f);
    if (t < SS / 4)        ((int4*)g_cnt)[t]   = make_int4(0, 0, 0, 0);
}

// ---------------------------------------------------------------------------
// Kernel: split x into transposed bf16 hi/lo pairs
// ---------------------------------------------------------------------------
__global__ void split_x_kernel(const float* __restrict__ x) {
    int t = blockIdx.x * 256 + threadIdx.x;       // 0 .. NN*FF-1
    int i = t >> 6, f = t & 63;
    float v = x[t];
    __nv_bfloat16 h = __float2bfloat16(v);
    float r = v - __bfloat162float(h);
    g_xThi[f * NN + i] = h;
    g_xTlo[f * NN + i] = __float2bfloat16(r);
}

// ---------------------------------------------------------------------------
// Kernel: per-structure tanh term + scatter into acc2
// ---------------------------------------------------------------------------
__global__ void struct_kernel(const float* __restrict__ x) {
    int wid = threadIdx.x >> 5, lid = threadIdx.x & 31;
    int s = blockIdx.x * 8 + wid;
    int m = g_cnt[s];
    if (m != 3 && m != 4 && m != 10) return;
    int mem[10];
    int first = 0x7FFFFFFF;
#pragma unroll 10
    for (int j = 0; j < 10; j++) {
        if (j < m) {
            mem[j] = g_members[s * 10 + j];
            first = min(first, mem[j]);
        }
    }
    float sa = 0.f, sb = 0.f;
    for (int j = 0; j < m; j++) {
        const float* xr = x + mem[j] * FF;
        sa += xr[lid];
        sb += xr[lid + 32];
    }
    const float* xf = x + first * FF;
    float fm = (float)m;
    float ta = tanhf(fm * xf[lid]      - sa) * K3c;
    float tb = tanhf(fm * xf[lid + 32] - sb) * K3c;
    for (int j = 0; j < m; j++) {
        atomicAdd(&g_acc2[mem[j] * FF + lid],      ta);
        atomicAdd(&g_acc2[mem[j] * FF + 32 + lid], tb);
    }
}

// ---------------------------------------------------------------------------
// Fused GEMM + incidence extraction (R6 structure, proven best — unchanged).
// GEMM: y = Lap @ x, mma.sync bf16-split (3 terms), cp.async 3-stage pipe.
// BM=64, BN=64, TKC=32, 128 threads (4 warps, 2x2), 4 CTAs/SM.
// grid = 2048 (128 mtiles x 8 ksplits x 2 matrices).
// ---------------------------------------------------------------------------
#define TKC 32
#define KSPLIT 8
#define KPER (NN / KSPLIT)          // 1024
#define GITERS (KPER / TKC)         // 32
#define NSTAGE 3
// stage: A fp32 64 rows x 160B = 10240; Bhi 64x64B = 4096; Blo 4096
#define A_ROW_B 160
#define B_OFF   10240
#define BL_OFF  14336
#define STAGE_BYTES 18432
#define GEMM_SMEM (NSTAGE * STAGE_BYTES)

// SW64 swizzle for 64B rows: chunk c (16B) at row r -> c ^ ((r>>1)&3)
#define SW64C(r, c) (((c) ^ (((r) >> 1) & 3)) << 4)

__device__ __forceinline__ void splitf2(float2 v, uint32_t& h, uint32_t& l) {
    __nv_bfloat162 hh = __float22bfloat162_rn(v);
    float hx = __bfloat162float(__low2bfloat16(hh));
    float hy = __bfloat162float(__high2bfloat16(hh));
    __nv_bfloat162 ll = __floats2bfloat162_rn(v.x - hx, v.y - hy);
    h = *(uint32_t*)&hh;
    l = *(uint32_t*)&ll;
}

__device__ __forceinline__ void issue_stage(const float* __restrict__ A,
                                            int m0, int k0, int tid,
                                            uint32_t sstage) {
    // A: 64 rows x 32 fp32 (128B = 8 x 16B chunks) -> 512 chunks, 4/thread
#pragma unroll
    for (int j = 0; j < 4; j++) {
        int q = tid + j * 128;
        int row = q >> 3, c = q & 7;
        uint32_t dst = sstage + row * A_ROW_B + c * 16;
        const float* src = A + (size_t)(m0 + row) * NN + k0 + c * 4;
        CP_ASYNC16(dst, src);
    }
    // B hi/lo: 64 rows x 32 bf16 = 64B/row, SW64 packed -> 256 chunks each
#pragma unroll
    for (int j = 0; j < 2; j++) {
        int q = tid + j * 128;
        int row = q >> 2, c = q & 3;
        uint32_t sw = (uint32_t)(row * 64 + SW64C(row, c));
        const char* srch = (const char*)(g_xThi + (size_t)row * NN + k0 + c * 8);
        const char* srcl = (const char*)(g_xTlo + (size_t)row * NN + k0 + c * 8);
        CP_ASYNC16(sstage + B_OFF + sw, srch);
        CP_ASYNC16(sstage + BL_OFF + sw, srcl);
    }
    CP_COMMIT();
}

__global__ void __launch_bounds__(128, 4)
gemm_extract_kernel(const float* __restrict__ lapP, const float* __restrict__ lapN,
                    const float* __restrict__ inc) {
    extern __shared__ char smem[];
    const int tid = threadIdx.x;
    const int wid = tid >> 5;
    const int lane = tid & 31;
    const int bid = blockIdx.x;
    const int mat = bid >> 10;
    const int rest = bid & 1023;
    const int ks = rest & 7;
    const int mtile = rest >> 3;
    const float* A = mat ? lapN : lapP;
    float* dst = g_ypart[mat * 8 + ks];
    const int m0 = mtile * 64;
    const int kb = ks * KPER;

    const int warp_m = (wid & 1) * 32;   // 2 warps along M
    const int warp_n = (wid >> 1) * 32;  // 2 warps along N

    const uint32_t sbase = smem_u32(smem);

    float acc[2][4][4];
#pragma unroll
    for (int mt = 0; mt < 2; mt++)
#pragma unroll
        for (int nt = 0; nt < 4; nt++)
#pragma unroll
            for (int j = 0; j < 4; j++) acc[mt][nt][j] = 0.f;

    // prologue: issue first NSTAGE-1 stages (data streams during extract)
    issue_stage(A, m0, kb, tid, sbase);
    issue_stage(A, m0, kb + TKC, tid, sbase + STAGE_BYTES);

    // ---- fused incidence extraction: this CTA's 8192-float4 slice ----
    {
        const float4* inc4 = (const float4*)inc;
        int base = bid * 8192;
        for (int j = 0; j < 64; j++) {
            int q = base + j * 128 + tid;
            float4 v = inc4[q];
            int e = q * 4;
            int i = e >> 13;        // row (node)
            int s = e & 8191;       // column (structure)
            float vv[4] = {v.x, v.y, v.z, v.w};
#pragma unroll
            for (int u = 0; u < 4; u++) {
                if (vv[u] != 0.0f) {
                    int p = atomicAdd(&g_cnt[s + u], 1);
                    if (p < 10) g_members[(s + u) * 10 + p] = i;
                }
            }
        }
    }

    // ---- GEMM mainloop ----
    for (int it = 0; it < GITERS; ++it) {
        CP_WAIT1();            // 2 groups pending -> stage `it` resident
        __syncthreads();

        if (it + NSTAGE - 1 < GITERS)
            issue_stage(A, m0, kb + (it + NSTAGE - 1) * TKC, tid,
                        sbase + ((it + NSTAGE - 1) % NSTAGE) * STAGE_BYTES);
        else
            CP_COMMIT();       // empty group keeps pending count at 2

        const uint32_t sstage = sbase + (it % NSTAGE) * STAGE_BYTES;
        const char* sa = smem + (it % NSTAGE) * STAGE_BYTES;

#pragma unroll
        for (int kc = 0; kc < 2; kc++) {
            // ---- A fragments: LDS fp32 + split in registers ----
            uint32_t ah[2][4], al[2][4];
#pragma unroll
            for (int mt = 0; mt < 2; mt++) {
                int row0 = warp_m + mt * 16 + (lane >> 2);
                int kbyt = kc * 64 + (lane & 3) * 8;
                const char* p = sa + row0 * A_ROW_B + kbyt;
                float2 v0 = *(const float2*)(p);
                float2 v1 = *(const float2*)(p + 8 * A_ROW_B);
                float2 v2 = *(const float2*)(p + 32);
                float2 v3 = *(const float2*)(p + 8 * A_ROW_B + 32);
                splitf2(v0, ah[mt][0], al[mt][0]);
                splitf2(v1, ah[mt][1], al[mt][1]);
                splitf2(v2, ah[mt][2], al[mt][2]);
                splitf2(v3, ah[mt][3], al[mt][3]);
            }
            // ---- B fragments via ldmatrix from SW64-packed rows ----
            uint32_t bh[2][4], bl[2][4];
#pragma unroll
            for (int nt2 = 0; nt2 < 2; nt2++) {
                uint32_t grp = lane >> 3;
                uint32_t nrow = warp_n + nt2 * 16 + (grp >> 1) * 8 + (lane & 7);
                uint32_t c = kc * 2 + (grp & 1);
                uint32_t off = nrow * 64 + SW64C(nrow, c);
                LDSM_X4(bh[nt2][0], bh[nt2][1], bh[nt2][2], bh[nt2][3],
                        sstage + B_OFF + off);
                LDSM_X4(bl[nt2][0], bl[nt2][1], bl[nt2][2], bl[nt2][3],
                        sstage + BL_OFF + off);
            }
#pragma unroll
            for (int mt = 0; mt < 2; mt++) {
#pragma unroll
                for (int nt = 0; nt < 4; nt++) {
                    int n2 = nt >> 1, p = (nt & 1) * 2;
                    MMA16816(acc[mt][nt], ah[mt], bh[n2][p], bh[n2][p + 1]);
                    MMA16816(acc[mt][nt], ah[mt], bl[n2][p], bl[n2][p + 1]);
                    MMA16816(acc[mt][nt], al[mt], bh[n2][p], bh[n2][p + 1]);
                }
            }
        }
    }

    // ---- epilogue: write partial results ----
#pragma unroll
    for (int mt = 0; mt < 2; mt++) {
#pragma unroll
        for (int nt = 0; nt < 4; nt++) {
            int r0 = m0 + warp_m + mt * 16 + (lane >> 2);
            int c0 = warp_n + nt * 8 + (lane & 3) * 2;
            *(float2*)(dst + (size_t)r0 * FF + c0) =
                make_float2(acc[mt][nt][0], acc[mt][nt][1]);
            *(float2*)(dst + (size_t)(r0 + 8) * FF + c0) =
                make_float2(acc[mt][nt][2], acc[mt][nt][3]);
        }
    }
}

// ---------------------------------------------------------------------------
// Final fused kernel (vectorized): each thread owns a float4 of features.
// out = (K0*x + K1*sin(yp) + K2*sin(yn) + acc2) @ W + bias
// 512 blocks x 256 threads; block handles 16 rows.
// ---------------------------------------------------------------------------
__global__ void final_kernel(const float* __restrict__ x, const float* __restrict__ w,
                             const float* __restrict__ bias, float* __restrict__ out) {
    __shared__ float wsm[FF * OO];       // 16KB
    __shared__ float vsm[16 * FF];       // 4KB
    const int tid = threadIdx.x;
    // load W as float4 (1024 float4, 4 per thread)
#pragma unroll
    for (int j = 0; j < 4; j++)
        ((float4*)wsm)[tid + j * 256] = ((const float4*)w)[tid + j * 256];

    const int r  = tid >> 4;             // 0..15 (row within block)
    const int fq = tid & 15;             // float4 index along features
    const int i  = blockIdx.x * 16 + r;
    const int idx4 = i * (FF / 4) + fq;  // float4 index into [N, F]

    float4 yp = make_float4(0.f, 0.f, 0.f, 0.f);
    float4 yn = make_float4(0.f, 0.f, 0.f, 0.f);
#pragma unroll
    for (int p = 0; p < 8; p++) {
        float4 t = ((const float4*)g_ypart[p])[idx4];
        yp.x += t.x; yp.y += t.y; yp.z += t.z; yp.w += t.w;
    }
#pragma unroll
    for (int p = 8; p < 16; p++) {
        float4 t = ((const float4*)g_ypart[p])[idx4];
        yn.x += t.x; yn.y += t.y; yn.z += t.z; yn.w += t.w;
    }
    float4 xv = ((const float4*)x)[idx4];
    float4 a2 = ((const float4*)g_acc2)[idx4];
    float4 v;
    v.x = K0c * xv.x + K1c * sinf(yp.x) + K2c * sinf(yn.x) + a2.x;
    v.y = K0c * xv.y + K1c * sinf(yp.y) + K2c * sinf(yn.y) + a2.y;
    v.z = K0c * xv.z + K1c * sinf(yp.z) + K2c * sinf(yn.z) + a2.z;
    v.w = K0c * xv.w + K1c * sinf(yp.w) + K2c * sinf(yn.w) + a2.w;
    ((float4*)vsm)[r * 16 + fq] = v;
    __syncthreads();

    // each thread computes out[i][fq*4 .. fq*4+3]
    float4 acc = ((const float4*)bias)[fq];
#pragma unroll
    for (int ff = 0; ff < FF; ff++) {
        float vv = vsm[r * FF + ff];
        float4 wv = ((const float4*)wsm)[ff * 16 + fq];
        acc.x += vv * wv.x;
        acc.y += vv * wv.y;
        acc.z += vv * wv.z;
        acc.w += vv * wv.w;
    }
    ((float4*)out)[idx4] = acc;
}

// ---------------------------------------------------------------------------
// Launch
// ---------------------------------------------------------------------------
extern "C" void kernel_launch(void* const* d_in, const int* in_sizes, int n_in,
                              void* d_out, int out_size) {
    const float* x    = (const float*)d_in[0];
    const float* lapP = (const float*)d_in[1];
    const float* lapN = (const float*)d_in[2];
    const float* inc  = (const float*)d_in[3];
    const float* w    = (const float*)d_in[4];
    const float* bias = (const float*)d_in[5];
    float* out = (float*)d_out;

    cudaFuncSetAttribute(gemm_extract_kernel,
                         cudaFuncAttributeMaxDynamicSharedMemorySize, GEMM_SMEM);

    zero_kernel<<<512, 256>>>();
    split_x_kernel<<<(NN * FF) / 256, 256>>>(x);
    gemm_extract_kernel<<<2048, 128, GEMM_SMEM>>>(lapP, lapN, inc);
    struct_kernel<<<SS / 8, 256>>>(x);
    final_kernel<<<NN / 16, 256>>>(x, w, bias, out);
}

// round 17
// speedup vs baseline: 1.1861x; 1.0085x over previous
#include <cuda_runtime.h>
#include <cuda_bf16.h>
#include <stdint.h>

// Problem constants
#define NN 8192      // nodes
#define SS 8192      // structures
#define FF 64        // features
#define OO 64        // out features
#define K0c 0.5f
#define K1c 0.05f
#define K2c (-0.05f)
#define K3c 0.05f

// ---------------------------------------------------------------------------
// Device scratch (static allocation — allowed)
// ---------------------------------------------------------------------------
__device__ __nv_bfloat16 g_xThi[FF * NN];   // x^T split hi  [f][k]
__device__ __nv_bfloat16 g_xTlo[FF * NN];   // x^T split lo  [f][k]
__device__ float g_ypart[16][NN * FF];      // [mat*8 + ksplit][n][f]
__device__ int   g_cnt[SS];
__device__ int   g_members[SS * 10];
__device__ float g_acc2[NN * FF];

// ---------------------------------------------------------------------------
// portable PTX helpers (no sm_103a-only features)
// ---------------------------------------------------------------------------
#define LDSM_X4(r0, r1, r2, r3, addr) \
    asm volatile("ldmatrix.sync.aligned.m8n8.x4.shared.b16 {%0,%1,%2,%3}, [%4];" \
                 : "=r"(r0), "=r"(r1), "=r"(r2), "=r"(r3) : "r"(addr))

#define MMA16816(c, a, b0, b1) \
    asm volatile("mma.sync.aligned.m16n8k16.row.col.f32.bf16.bf16.f32 " \
                 "{%0,%1,%2,%3}, {%4,%5,%6,%7}, {%8,%9}, {%0,%1,%2,%3};" \
                 : "+f"((c)[0]), "+f"((c)[1]), "+f"((c)[2]), "+f"((c)[3]) \
                 : "r"((a)[0]), "r"((a)[1]), "r"((a)[2]), "r"((a)[3]), \
                   "r"(b0), "r"(b1))

#define CP_ASYNC16(dst, src) \
    asm volatile("cp.async.cg.shared.global [%0], [%1], 16;" \
                 :: "r"(dst), "l"(src) : "memory")
#define CP_COMMIT() asm volatile("cp.async.commit_group;" ::: "memory")
#define CP_WAIT1()  asm volatile("cp.async.wait_group 1;" ::: "memory")

__device__ __forceinline__ uint32_t smem_u32(const void* p) {
    return (uint32_t)__cvta_generic_to_shared(p);
}

// streaming store (evict-first): partial results consumed exactly once
__device__ __forceinline__ void stwt2(float* p, float a, float b) {
    asm volatile("st.global.wt.v2.f32 [%0], {%1, %2};" :: "l"(p), "f"(a), "f"(b)
                 : "memory");
}

// ---------------------------------------------------------------------------
// Kernel: split x into transposed bf16 hi/lo pairs + zero accumulators
// (grid covers NN*FF = 524288 threads; acc2 has same count, cnt is smaller)
// ---------------------------------------------------------------------------
__global__ void split_x_kernel(const float* __restrict__ x) {
    int t = blockIdx.x * 256 + threadIdx.x;       // 0 .. NN*FF-1
    int i = t >> 6, f = t & 63;
    float v = x[t];
    __nv_bfloat16 h = __float2bfloat16(v);
    float r = v - __bfloat162float(h);
    g_xThi[f * NN + i] = h;
    g_xTlo[f * NN + i] = __float2bfloat16(r);
    g_acc2[t] = 0.f;
    if (t < SS) g_cnt[t] = 0;
}

// ---------------------------------------------------------------------------
// Kernel: per-structure tanh term + scatter into acc2
// ---------------------------------------------------------------------------
__global__ void struct_kernel(const float* __restrict__ x) {
    int wid = threadIdx.x >> 5, lid = threadIdx.x & 31;
    int s = blockIdx.x * 8 + wid;
    int m = g_cnt[s];
    if (m != 3 && m != 4 && m != 10) return;
    int mem[10];
    int first = 0x7FFFFFFF;
    for (int j = 0; j < m; j++) {
        mem[j] = g_members[s * 10 + j];
        first = min(first, mem[j]);
    }
    // issue the pivot-row loads early so they overlap the member-sum loop
    const float* xf = x + first * FF;
    float xa = xf[lid], xb = xf[lid + 32];
    float sa = 0.f, sb = 0.f;
    for (int j = 0; j < m; j++) {
        const float* xr = x + mem[j] * FF;
        sa += xr[lid];
        sb += xr[lid + 32];
    }
    float fm = (float)m;
    float ta = tanhf(fm * xa - sa) * K3c;
    float tb = tanhf(fm * xb - sb) * K3c;
    for (int j = 0; j < m; j++) {
        atomicAdd(&g_acc2[mem[j] * FF + lid],      ta);
        atomicAdd(&g_acc2[mem[j] * FF + 32 + lid], tb);
    }
}

// ---------------------------------------------------------------------------
// Fused GEMM + incidence extraction (R6 structure, proven best — unchanged).
// GEMM: y = Lap @ x, mma.sync bf16-split (3 terms), cp.async 3-stage pipe.
// BM=64, BN=64, TKC=32, 128 threads (4 warps, 2x2), 4 CTAs/SM.
// grid = 2048 (128 mtiles x 8 ksplits x 2 matrices).
// ---------------------------------------------------------------------------
#define TKC 32
#define KSPLIT 8
#define KPER (NN / KSPLIT)          // 1024
#define GITERS (KPER / TKC)         // 32
#define NSTAGE 3
// stage: A fp32 64 rows x 160B = 10240; Bhi 64x64B = 4096; Blo 4096
#define A_ROW_B 160
#define B_OFF   10240
#define BL_OFF  14336
#define STAGE_BYTES 18432
#define GEMM_SMEM (NSTAGE * STAGE_BYTES)

// SW64 swizzle for 64B rows: chunk c (16B) at row r -> c ^ ((r>>1)&3)
#define SW64C(r, c) (((c) ^ (((r) >> 1) & 3)) << 4)

__device__ __forceinline__ void splitf2(float2 v, uint32_t& h, uint32_t& l) {
    __nv_bfloat162 hh = __float22bfloat162_rn(v);
    float hx = __bfloat162float(__low2bfloat16(hh));
    float hy = __bfloat162float(__high2bfloat16(hh));
    __nv_bfloat162 ll = __floats2bfloat162_rn(v.x - hx, v.y - hy);
    h = *(uint32_t*)&hh;
    l = *(uint32_t*)&ll;
}

__device__ __forceinline__ void issue_stage(const float* __restrict__ A,
                                            int m0, int k0, int tid,
                                            uint32_t sstage) {
    // A: 64 rows x 32 fp32 (128B = 8 x 16B chunks) -> 512 chunks, 4/thread
#pragma unroll
    for (int j = 0; j < 4; j++) {
        int q = tid + j * 128;
        int row = q >> 3, c = q & 7;
        uint32_t dst = sstage + row * A_ROW_B + c * 16;
        const float* src = A + (size_t)(m0 + row) * NN + k0 + c * 4;
        CP_ASYNC16(dst, src);
    }
    // B hi/lo: 64 rows x 32 bf16 = 64B/row, SW64 packed -> 256 chunks each
#pragma unroll
    for (int j = 0; j < 2; j++) {
        int q = tid + j * 128;
        int row = q >> 2, c = q & 3;
        uint32_t sw = (uint32_t)(row * 64 + SW64C(row, c));
        const char* srch = (const char*)(g_xThi + (size_t)row * NN + k0 + c * 8);
        const char* srcl = (const char*)(g_xTlo + (size_t)row * NN + k0 + c * 8);
        CP_ASYNC16(sstage + B_OFF + sw, srch);
        CP_ASYNC16(sstage + BL_OFF + sw, srcl);
    }
    CP_COMMIT();
}

__global__ void __launch_bounds__(128, 4)
gemm_extract_kernel(const float* __restrict__ lapP, const float* __restrict__ lapN,
                    const float* __restrict__ inc) {
    extern __shared__ char smem[];
    const int tid = threadIdx.x;
    const int wid = tid >> 5;
    const int lane = tid & 31;
    const int bid = blockIdx.x;
    const int mat = bid >> 10;
    const int rest = bid & 1023;
    const int ks = rest & 7;
    const int mtile = rest >> 3;
    const float* A = mat ? lapN : lapP;
    float* dst = g_ypart[mat * 8 + ks];
    const int m0 = mtile * 64;
    const int kb = ks * KPER;

    const int warp_m = (wid & 1) * 32;   // 2 warps along M
    const int warp_n = (wid >> 1) * 32;  // 2 warps along N

    const uint32_t sbase = smem_u32(smem);

    float acc[2][4][4];
#pragma unroll
    for (int mt = 0; mt < 2; mt++)
#pragma unroll
        for (int nt = 0; nt < 4; nt++)
#pragma unroll
            for (int j = 0; j < 4; j++) acc[mt][nt][j] = 0.f;

    // prologue: issue first NSTAGE-1 stages (data streams during extract)
    issue_stage(A, m0, kb, tid, sbase);
    issue_stage(A, m0, kb + TKC, tid, sbase + STAGE_BYTES);

    // ---- fused incidence extraction: this CTA's 8192-float4 slice ----
    {
        const float4* inc4 = (const float4*)inc;
        int base = bid * 8192;
        for (int j = 0; j < 64; j++) {
            int q = base + j * 128 + tid;
            float4 v = inc4[q];
            int e = q * 4;
            int i = e >> 13;        // row (node)
            int s = e & 8191;       // column (structure)
            float vv[4] = {v.x, v.y, v.z, v.w};
#pragma unroll
            for (int u = 0; u < 4; u++) {
                if (vv[u] != 0.0f) {
                    int p = atomicAdd(&g_cnt[s + u], 1);
                    if (p < 10) g_members[(s + u) * 10 + p] = i;
                }
            }
        }
    }

    // ---- GEMM mainloop ----
    for (int it = 0; it < GITERS; ++it) {
        CP_WAIT1();            // 2 groups pending -> stage `it` resident
        __syncthreads();

        if (it + NSTAGE - 1 < GITERS)
            issue_stage(A, m0, kb + (it + NSTAGE - 1) * TKC, tid,
                        sbase + ((it + NSTAGE - 1) % NSTAGE) * STAGE_BYTES);
        else
            CP_COMMIT();       // empty group keeps pending count at 2

        const uint32_t sstage = sbase + (it % NSTAGE) * STAGE_BYTES;
        const char* sa = smem + (it % NSTAGE) * STAGE_BYTES;

#pragma unroll
        for (int kc = 0; kc < 2; kc++) {
            // ---- A fragments: LDS fp32 + split in registers ----
            uint32_t ah[2][4], al[2][4];
#pragma unroll
            for (int mt = 0; mt < 2; mt++) {
                int row0 = warp_m + mt * 16 + (lane >> 2);
                int kbyt = kc * 64 + (lane & 3) * 8;
                const char* p = sa + row0 * A_ROW_B + kbyt;
                float2 v0 = *(const float2*)(p);
                float2 v1 = *(const float2*)(p + 8 * A_ROW_B);
                float2 v2 = *(const float2*)(p + 32);
                float2 v3 = *(const float2*)(p + 8 * A_ROW_B + 32);
                splitf2(v0, ah[mt][0], al[mt][0]);
                splitf2(v1, ah[mt][1], al[mt][1]);
                splitf2(v2, ah[mt][2], al[mt][2]);
                splitf2(v3, ah[mt][3], al[mt][3]);
            }
            // ---- B fragments via ldmatrix from SW64-packed rows ----
            uint32_t bh[2][4], bl[2][4];
#pragma unroll
            for (int nt2 = 0; nt2 < 2; nt2++) {
                uint32_t grp = lane >> 3;
                uint32_t nrow = warp_n + nt2 * 16 + (grp >> 1) * 8 + (lane & 7);
                uint32_t c = kc * 2 + (grp & 1);
                uint32_t off = nrow * 64 + SW64C(nrow, c);
                LDSM_X4(bh[nt2][0], bh[nt2][1], bh[nt2][2], bh[nt2][3],
                        sstage + B_OFF + off);
                LDSM_X4(bl[nt2][0], bl[nt2][1], bl[nt2][2], bl[nt2][3],
                        sstage + BL_OFF + off);
            }
#pragma unroll
            for (int mt = 0; mt < 2; mt++) {
#pragma unroll
                for (int nt = 0; nt < 4; nt++) {
                    int n2 = nt >> 1, p = (nt & 1) * 2;
                    MMA16816(acc[mt][nt], ah[mt], bh[n2][p], bh[n2][p + 1]);
                    MMA16816(acc[mt][nt], ah[mt], bl[n2][p], bl[n2][p + 1]);
                    MMA16816(acc[mt][nt], al[mt], bh[n2][p], bh[n2][p + 1]);
                }
            }
        }
    }

    // ---- epilogue: streaming (evict-first) stores of partial results ----
#pragma unroll
    for (int mt = 0; mt < 2; mt++) {
#pragma unroll
        for (int nt = 0; nt < 4; nt++) {
            int r0 = m0 + warp_m + mt * 16 + (lane >> 2);
            int c0 = warp_n + nt * 8 + (lane & 3) * 2;
            stwt2(dst + (size_t)r0 * FF + c0, acc[mt][nt][0], acc[mt][nt][1]);
            stwt2(dst + (size_t)(r0 + 8) * FF + c0, acc[mt][nt][2], acc[mt][nt][3]);
        }
    }
}

// ---------------------------------------------------------------------------
// Final fused kernel (vectorized): each thread owns a float4 of features.
// out = (K0*x + K1*sin(yp) + K2*sin(yn) + acc2) @ W + bias
// 512 blocks x 256 threads; block handles 16 rows.
// ---------------------------------------------------------------------------
__global__ void final_kernel(const float* __restrict__ x, const float* __restrict__ w,
                             const float* __restrict__ bias, float* __restrict__ out) {
    __shared__ float wsm[FF * OO];       // 16KB
    __shared__ float vsm[16 * FF];       // 4KB
    const int tid = threadIdx.x;
    // load W as float4 (1024 float4, 4 per thread)
#pragma unroll
    for (int j = 0; j < 4; j++)
        ((float4*)wsm)[tid + j * 256] = ((const float4*)w)[tid + j * 256];

    const int r  = tid >> 4;             // 0..15 (row within block)
    const int fq = tid & 15;             // float4 index along features
    const int i  = blockIdx.x * 16 + r;
    const int idx4 = i * (FF / 4) + fq;  // float4 index into [N, F]

    float4 yp = make_float4(0.f, 0.f, 0.f, 0.f);
    float4 yn = make_float4(0.f, 0.f, 0.f, 0.f);
#pragma unroll
    for (int p = 0; p < 8; p++) {
        float4 t = ((const float4*)g_ypart[p])[idx4];
        yp.x += t.x; yp.y += t.y; yp.z += t.z; yp.w += t.w;
    }
#pragma unroll
    for (int p = 8; p < 16; p++) {
        float4 t = ((const float4*)g_ypart[p])[idx4];
        yn.x += t.x; yn.y += t.y; yn.z += t.z; yn.w += t.w;
    }
    float4 xv = ((const float4*)x)[idx4];
    float4 a2 = ((const float4*)g_acc2)[idx4];
    float4 v;
    v.x = K0c * xv.x + K1c * sinf(yp.x) + K2c * sinf(yn.x) + a2.x;
    v.y = K0c * xv.y + K1c * sinf(yp.y) + K2c * sinf(yn.y) + a2.y;
    v.z = K0c * xv.z + K1c * sinf(yp.z) + K2c * sinf(yn.z) + a2.z;
    v.w = K0c * xv.w + K1c * sinf(yp.w) + K2c * sinf(yn.w) + a2.w;
    ((float4*)vsm)[r * 16 + fq] = v;
    __syncthreads();

    // each thread computes out[i][fq*4 .. fq*4+3]
    float4 acc = ((const float4*)bias)[fq];
#pragma unroll
    for (int ff = 0; ff < FF; ff++) {
        float vv = vsm[r * FF + ff];
        float4 wv = ((const float4*)wsm)[ff * 16 + fq];
        acc.x += vv * wv.x;
        acc.y += vv * wv.y;
        acc.z += vv * wv.z;
        acc.w += vv * wv.w;
    }
    ((float4*)out)[idx4] = acc;
}

// ---------------------------------------------------------------------------
// Launch
// ---------------------------------------------------------------------------
extern "C" void kernel_launch(void* const* d_in, const int* in_sizes, int n_in,
                              void* d_out, int out_size) {
    const float* x    = (const float*)d_in[0];
    const float* lapP = (const float*)d_in[1];
    const float* lapN = (const float*)d_in[2];
    const float* inc  = (const float*)d_in[3];
    const float* w    = (const float*)d_in[4];
    const float* bias = (const float*)d_in[5];
    float* out = (float*)d_out;

    cudaFuncSetAttribute(gemm_extract_kernel,
                         cudaFuncAttributeMaxDynamicSharedMemorySize, GEMM_SMEM);

    split_x_kernel<<<(NN * FF) / 256, 256>>>(x);
    gemm_extract_kernel<<<2048, 128, GEMM_SMEM>>>(lapP, lapN, inc);
    struct_kernel<<<SS / 8, 256>>>(x);
    final_kernel<<<NN / 16, 256>>>(x, w, bias, out);
}